// round 13
// baseline (speedup 1.0000x reference)
#include <cuda_runtime.h>
#include <math.h>
#include <stdint.h>

// ---------------- problem constants ----------------
#define BATCH   4
#define SEQ     2048
#define DMODEL  1024
#define NHEADS  16
#define DK      64
#define MROWS   (BATCH * SEQ)      // 8192
#define QKVCOLS (3 * DMODEL)       // 3072

// ---------------- scratch ----------------
__device__ float g_qkv[(size_t)MROWS * QKVCOLS];    // 96 MB (tf32-rounded by GEMM1)
__device__ float g_attn[(size_t)MROWS * DMODEL];    // 32 MB (tf32-rounded at write)
__device__ float g_xr[(size_t)MROWS * DMODEL];      // 32 MB (tf32-rounded x)
__device__ float g_wq[(size_t)DMODEL * QKVCOLS];    // 12 MB (rounded)
__device__ float g_wo[(size_t)DMODEL * DMODEL];     //  4 MB (rounded)

// ---------------- helpers ----------------
__device__ __forceinline__ uint32_t f2tf(float x) {
    uint32_t r;
    asm("cvt.rna.tf32.f32 %0, %1;" : "=r"(r) : "f"(x));
    return r;
}
__device__ __forceinline__ uint32_t smem_u32(const void* p) {
    uint32_t a;
    asm("{ .reg .u64 t; cvta.to.shared.u64 t, %1; cvt.u32.u64 %0, t; }" : "=r"(a) : "l"(p));
    return a;
}
__device__ __forceinline__ void cp16(uint32_t dst, const void* src) {
    asm volatile("cp.async.cg.shared.global [%0], [%1], 16;" :: "r"(dst), "l"(src));
}
__device__ __forceinline__ void cp_commit() { asm volatile("cp.async.commit_group;"); }
__device__ __forceinline__ void cp_wait0()  { asm volatile("cp.async.wait_group 0;"); }
__device__ __forceinline__ void cp_wait2()  { asm volatile("cp.async.wait_group 2;"); }

// D(16x8) += A(16x8 row) * B(8x8 col), tf32 in, fp32 accum
__device__ __forceinline__ void mma8(float* c, const uint32_t* a, const uint32_t* b) {
    asm volatile(
        "mma.sync.aligned.m16n8k8.row.col.f32.tf32.tf32.f32 "
        "{%0,%1,%2,%3}, {%4,%5,%6,%7}, {%8,%9}, {%0,%1,%2,%3};"
        : "+f"(c[0]), "+f"(c[1]), "+f"(c[2]), "+f"(c[3])
        : "r"(a[0]), "r"(a[1]), "r"(a[2]), "r"(a[3]), "r"(b[0]), "r"(b[1]));
}

// =================================================================
// TF32 GEMM via mma.sync, cp.async 4-stage pipeline.
// C[M,N] = A[M,K] @ B[K,N], row-major fp32 (pre-rounded to tf32).
// Block 128x256, 256 thr = 8 warps (2x4), warp tile 64x64, BK=32.
// ROUND: tf32-round C on store (for GEMM1 -> attention raw streaming).
// =================================================================
#define GST 4
#define ASTR 36                 // A smem row stride (== 4 mod 32)
#define BSTR 264                // B smem row stride (== 8 mod 32)
#define ASZ (128 * ASTR)        // u32 per stage
#define BSZ (32 * BSTR)
#define GSMEM ((GST * (ASZ + BSZ)) * 4)   // 208896 B

template <int ROUND>
__global__ __launch_bounds__(256, 1)
void gemm_tf32_ca(const float* __restrict__ A, const float* __restrict__ B,
                  float* __restrict__ C, int N, int K)
{
    extern __shared__ uint32_t sm[];
    uint32_t* Asm = sm;                     // [GST][ASZ]
    uint32_t* Bsm = sm + GST * ASZ;         // [GST][BSZ]
    const uint32_t sA = smem_u32(Asm);
    const uint32_t sB = smem_u32(Bsm);

    const int tid  = threadIdx.x, lane = tid & 31, warp = tid >> 5;
    const int g    = lane >> 2, tig = lane & 3;
    const int wr   = warp >> 2, wc  = warp & 3;     // 2 x 4 warp grid
    const int bm   = blockIdx.y * 128, bn = blockIdx.x * 256;
    const int NK   = K / 32;

    auto issue = [&](int s, int kt) {
        const float* Ag = A + (size_t)bm * K + kt * 32;
        const float* Bg = B + (size_t)(kt * 32) * N + bn;
        const uint32_t ao = sA + s * ASZ * 4;
        const uint32_t bo = sB + s * BSZ * 4;
        #pragma unroll
        for (int j = 0; j < 4; j++) {                 // A: 1024 x 16B
            int idx = tid + j * 256;
            int row = idx >> 3, cc = (idx & 7) * 4;
            cp16(ao + (row * ASTR + cc) * 4, Ag + (size_t)row * K + cc);
        }
        #pragma unroll
        for (int j = 0; j < 8; j++) {                 // B: 2048 x 16B
            int idx = tid + j * 256;
            int row = idx >> 6, cc = (idx & 63) * 4;
            cp16(bo + (row * BSTR + cc) * 4, Bg + (size_t)row * N + cc);
        }
        cp_commit();
    };

    float acc[4][8][4];
    #pragma unroll
    for (int mt = 0; mt < 4; mt++)
        #pragma unroll
        for (int nt = 0; nt < 8; nt++)
            #pragma unroll
            for (int j = 0; j < 4; j++) acc[mt][nt][j] = 0.0f;

    issue(0, 0);
    issue(1, 1);
    issue(2, 2);

    for (int kt = 0; kt < NK; kt++) {
        cp_wait2();            // tile kt resident (<=2 newer groups pending)
        __syncthreads();
        if (kt + 3 < NK) issue((kt + 3) & 3, kt + 3);
        else             cp_commit();   // uniform group accounting

        const uint32_t* Ab = Asm + (kt & 3) * ASZ;
        const uint32_t* Bb = Bsm + (kt & 3) * BSZ;

        #pragma unroll
        for (int kc = 0; kc < 4; kc++) {
            uint32_t a[4][4], b[8][2];
            #pragma unroll
            for (int mt = 0; mt < 4; mt++) {
                const uint32_t* p = Ab + (wr * 64 + mt * 16 + g) * ASTR + kc * 8 + tig;
                a[mt][0] = p[0];
                a[mt][1] = p[8 * ASTR];
                a[mt][2] = p[4];
                a[mt][3] = p[8 * ASTR + 4];
            }
            #pragma unroll
            for (int nt = 0; nt < 8; nt++) {
                const uint32_t* p = Bb + (kc * 8 + tig) * BSTR + wc * 64 + nt * 8 + g;
                b[nt][0] = p[0];
                b[nt][1] = p[4 * BSTR];
            }
            #pragma unroll
            for (int mt = 0; mt < 4; mt++)
                #pragma unroll
                for (int nt = 0; nt < 8; nt++)
                    mma8(acc[mt][nt], a[mt], b[nt]);
        }
    }

    #pragma unroll
    for (int mt = 0; mt < 4; mt++) {
        int row = bm + wr * 64 + mt * 16 + g;
        #pragma unroll
        for (int nt = 0; nt < 8; nt++) {
            int col = bn + wc * 64 + nt * 8 + 2 * tig;
            if (ROUND) {
                *(float2*)(C + (size_t)row * N + col) =
                    make_float2(__uint_as_float(f2tf(acc[mt][nt][0])),
                                __uint_as_float(f2tf(acc[mt][nt][1])));
                *(float2*)(C + (size_t)(row + 8) * N + col) =
                    make_float2(__uint_as_float(f2tf(acc[mt][nt][2])),
                                __uint_as_float(f2tf(acc[mt][nt][3])));
            } else {
                *(float2*)(C + (size_t)row * N + col) =
                    make_float2(acc[mt][nt][0], acc[mt][nt][1]);
                *(float2*)(C + (size_t)(row + 8) * N + col) =
                    make_float2(acc[mt][nt][2], acc[mt][nt][3]);
            }
        }
    }
}

// =================================================================
// prep: elementwise tf32 (RNA) rounding
// =================================================================
__global__ void round_tf32_kernel(const float4* __restrict__ in,
                                  float4* __restrict__ out, int n4)
{
    int i = blockIdx.x * blockDim.x + threadIdx.x;
    if (i < n4) {
        float4 v = in[i];
        out[i] = make_float4(__uint_as_float(f2tf(v.x)), __uint_as_float(f2tf(v.y)),
                             __uint_as_float(f2tf(v.z)), __uint_as_float(f2tf(v.w)));
    }
}

// =================================================================
// TF32 flash attention v2, causal.
// BR=128, BC=64, 256 thr (8 warps); warp w owns q rows [16w, 16w+16).
// qkv is pre-rounded tf32 -> K/V streamed raw via 2-stage cp.async.
// Scale 1/sqrt(dk)=0.125 applied post-MMA (exact, bit-identical).
// smem: Ps[128x68] (Q staging then P), K[2][64x68], V[2][64x68] = 104448 B
// =================================================================
#define FBR 128
#define FBC 64
#define FPST 68
#define FKST 68
#define FSTG (64 * FKST)                    // u32 per K/V stage
#define FSMEM ((128 * FPST + 4 * FSTG) * 4) // 104448 B

__global__ __launch_bounds__(256)
void flash_tf32(const float* __restrict__ qkv, float* __restrict__ outp)
{
    extern __shared__ uint32_t smf[];
    uint32_t* Ps  = smf;                    // 128 x FPST
    uint32_t* Kst = smf + 128 * FPST;       // [2][64 x FKST]
    uint32_t* Vst = Kst + 2 * FSTG;
    const uint32_t sK = smem_u32(Kst);
    const uint32_t sV = smem_u32(Vst);

    const int tid  = threadIdx.x;
    const int lane = tid & 31, warp = tid >> 5;
    const int g    = lane >> 2, tig = lane & 3;
    const int bh   = blockIdx.y, b = bh >> 4, h = bh & 15;
    const int qt   = gridDim.x - 1 - blockIdx.x;   // heavy tiles first
    const int q0   = qt * FBR;
    const int ktmax = 2 * qt + 1;                  // keys 0 .. q0+127

    const float* Qb = qkv + (size_t)b * SEQ * QKVCOLS + h * DK;
    const float* Kb = Qb + DMODEL;
    const float* Vb = Qb + 2 * DMODEL;

    auto issue_kv = [&](int s, int kt) {
        const float* Kg = Kb + (size_t)(kt * FBC) * QKVCOLS;
        const float* Vg = Vb + (size_t)(kt * FBC) * QKVCOLS;
        const uint32_t ko = sK + s * FSTG * 4;
        const uint32_t vo = sV + s * FSTG * 4;
        #pragma unroll
        for (int j = 0; j < 4; j++) {       // 64 rows x 16 float4, 256 thr
            int idx = tid + j * 256;
            int row = idx >> 4, c4 = (idx & 15) * 4;
            cp16(ko + (row * FKST + c4) * 4, Kg + (size_t)row * QKVCOLS + c4);
            cp16(vo + (row * FKST + c4) * 4, Vg + (size_t)row * QKVCOLS + c4);
        }
        cp_commit();
    };

    issue_kv(0, 0);   // get tile 0 flying before Q staging

    // stage Q (raw pre-rounded bits) into Ps
    for (int i = tid; i < FBR * 16; i += 256) {
        int row = i >> 4, c4 = (i & 15) * 4;
        *(uint4*)&Ps[row * FPST + c4] =
            *(const uint4*)(Qb + (size_t)(q0 + row) * QKVCOLS + c4);
    }
    __syncthreads();

    // extract this warp's Q fragments (rows warp*16 + {g, g+8})
    uint32_t aq[8][4];
    #pragma unroll
    for (int kc = 0; kc < 8; kc++) {
        const uint32_t* p = Ps + (warp * 16 + g) * FPST + kc * 8 + tig;
        aq[kc][0] = p[0];
        aq[kc][1] = p[8 * FPST];
        aq[kc][2] = p[4];
        aq[kc][3] = p[8 * FPST + 4];
    }

    float m0 = -INFINITY, m1 = -INFINITY, l0 = 0.0f, l1 = 0.0f;
    float o[8][4];
    #pragma unroll
    for (int nt = 0; nt < 8; nt++)
        #pragma unroll
        for (int j = 0; j < 4; j++) o[nt][j] = 0.0f;

    for (int kt = 0; kt <= ktmax; kt++) {
        const int k0 = kt * FBC;

        cp_wait0();            // this thread's tile-kt copies done
        __syncthreads();       // all threads' copies visible; prev compute done
        if (kt < ktmax) issue_kv((kt + 1) & 1, kt + 1);   // overlap next load

        // fully-masked warp-tile? (diagonal upper half) -> skip all compute
        const bool active = (k0 <= q0 + warp * 16 + 15);
        if (active) {
            const uint32_t* Kb_s = Kst + (kt & 1) * FSTG;
            const uint32_t* Vb_s = Vst + (kt & 1) * FSTG;

            // S = Q K^T
            float s[8][4];
            #pragma unroll
            for (int nt = 0; nt < 8; nt++) {
                s[nt][0] = s[nt][1] = s[nt][2] = s[nt][3] = 0.0f;
                #pragma unroll
                for (int kc = 0; kc < 8; kc++) {
                    uint32_t bk[2];
                    const uint32_t* p = Kb_s + (nt * 8 + g) * FKST + kc * 8 + tig;
                    bk[0] = p[0];
                    bk[1] = p[4];
                    mma8(s[nt], aq[kc], bk);
                }
            }

            // scale (exact 2^-3) then causal mask if tile touches diagonal
            #pragma unroll
            for (int nt = 0; nt < 8; nt++) {
                s[nt][0] *= 0.125f; s[nt][1] *= 0.125f;
                s[nt][2] *= 0.125f; s[nt][3] *= 0.125f;
            }
            if (k0 + FBC - 1 > q0 + warp * 16) {
                int qr0 = q0 + warp * 16 + g;
                #pragma unroll
                for (int nt = 0; nt < 8; nt++) {
                    int kc2 = k0 + nt * 8 + 2 * tig;
                    if (kc2     > qr0)     s[nt][0] = -INFINITY;
                    if (kc2 + 1 > qr0)     s[nt][1] = -INFINITY;
                    if (kc2     > qr0 + 8) s[nt][2] = -INFINITY;
                    if (kc2 + 1 > qr0 + 8) s[nt][3] = -INFINITY;
                }
            }

            // online softmax (rows g, g+8; quad reduce lanes tig 0..3)
            float mt0 = -INFINITY, mt1 = -INFINITY;
            #pragma unroll
            for (int nt = 0; nt < 8; nt++) {
                mt0 = fmaxf(mt0, fmaxf(s[nt][0], s[nt][1]));
                mt1 = fmaxf(mt1, fmaxf(s[nt][2], s[nt][3]));
            }
            mt0 = fmaxf(mt0, __shfl_xor_sync(0xffffffffu, mt0, 1));
            mt0 = fmaxf(mt0, __shfl_xor_sync(0xffffffffu, mt0, 2));
            mt1 = fmaxf(mt1, __shfl_xor_sync(0xffffffffu, mt1, 1));
            mt1 = fmaxf(mt1, __shfl_xor_sync(0xffffffffu, mt1, 2));

            float mn0 = fmaxf(m0, mt0), mn1 = fmaxf(m1, mt1);
            float al0 = __expf(m0 - mn0), al1 = __expf(m1 - mn1);

            float rs0 = 0.0f, rs1 = 0.0f;
            #pragma unroll
            for (int nt = 0; nt < 8; nt++) {
                s[nt][0] = __expf(s[nt][0] - mn0);
                s[nt][1] = __expf(s[nt][1] - mn0);
                s[nt][2] = __expf(s[nt][2] - mn1);
                s[nt][3] = __expf(s[nt][3] - mn1);
                rs0 += s[nt][0] + s[nt][1];
                rs1 += s[nt][2] + s[nt][3];
            }
            rs0 += __shfl_xor_sync(0xffffffffu, rs0, 1);
            rs0 += __shfl_xor_sync(0xffffffffu, rs0, 2);
            rs1 += __shfl_xor_sync(0xffffffffu, rs1, 1);
            rs1 += __shfl_xor_sync(0xffffffffu, rs1, 2);

            l0 = l0 * al0 + rs0;
            l1 = l1 * al1 + rs1;
            m0 = mn0;
            m1 = mn1;
            #pragma unroll
            for (int nt = 0; nt < 8; nt++) {
                o[nt][0] *= al0; o[nt][1] *= al0;
                o[nt][2] *= al1; o[nt][3] *= al1;
            }

            // P (tf32) to this warp's private Ps rows, then PV
            __syncwarp();
            {
                uint32_t* pr0 = Ps + (warp * 16 + g) * FPST;
                uint32_t* pr1 = pr0 + 8 * FPST;
                #pragma unroll
                for (int nt = 0; nt < 8; nt++) {
                    int c = nt * 8 + 2 * tig;
                    pr0[c]     = f2tf(s[nt][0]);
                    pr0[c + 1] = f2tf(s[nt][1]);
                    pr1[c]     = f2tf(s[nt][2]);
                    pr1[c + 1] = f2tf(s[nt][3]);
                }
            }
            __syncwarp();

            #pragma unroll
            for (int kc = 0; kc < 8; kc++) {
                uint32_t ap[4];
                const uint32_t* pp = Ps + (warp * 16 + g) * FPST + kc * 8 + tig;
                ap[0] = pp[0];
                ap[1] = pp[8 * FPST];
                ap[2] = pp[4];
                ap[3] = pp[8 * FPST + 4];
                #pragma unroll
                for (int nt = 0; nt < 8; nt++) {
                    uint32_t bv[2];
                    const uint32_t* pv = Vb_s + (kc * 8 + tig) * FKST + nt * 8 + g;
                    bv[0] = pv[0];
                    bv[1] = pv[4 * FKST];
                    mma8(o[nt], ap, bv);
                }
            }
        }
    }

    // normalize + tf32-round + write (GEMM2 streams these bits raw)
    float i0 = 1.0f / l0, i1 = 1.0f / l1;
    int r0 = q0 + warp * 16 + g;
    float* dst0 = outp + (size_t)(b * SEQ + r0) * DMODEL + h * DK;
    float* dst1 = dst0 + (size_t)8 * DMODEL;
    #pragma unroll
    for (int nt = 0; nt < 8; nt++) {
        int c = nt * 8 + 2 * tig;
        *(float2*)(dst0 + c) = make_float2(__uint_as_float(f2tf(o[nt][0] * i0)),
                                           __uint_as_float(f2tf(o[nt][1] * i0)));
        *(float2*)(dst1 + c) = make_float2(__uint_as_float(f2tf(o[nt][2] * i1)),
                                           __uint_as_float(f2tf(o[nt][3] * i1)));
    }
}

// =================================================================
// kernel_launch
// =================================================================
extern "C" void kernel_launch(void* const* d_in, const int* in_sizes, int n_in,
                              void* d_out, int out_size)
{
    const float* x     = (const float*)d_in[0];
    const float* w_qkv = (const float*)d_in[1];
    const float* w_out = (const float*)d_in[2];
    float*       out   = (float*)d_out;

    float *qkv_buf, *attn_buf, *xr, *wq, *wo;
    cudaGetSymbolAddress((void**)&qkv_buf,  g_qkv);
    cudaGetSymbolAddress((void**)&attn_buf, g_attn);
    cudaGetSymbolAddress((void**)&xr,       g_xr);
    cudaGetSymbolAddress((void**)&wq,       g_wq);
    cudaGetSymbolAddress((void**)&wo,       g_wo);

    cudaFuncSetAttribute(gemm_tf32_ca<1>, cudaFuncAttributeMaxDynamicSharedMemorySize, GSMEM);
    cudaFuncSetAttribute(gemm_tf32_ca<0>, cudaFuncAttributeMaxDynamicSharedMemorySize, GSMEM);
    cudaFuncSetAttribute(flash_tf32, cudaFuncAttributeMaxDynamicSharedMemorySize, FSMEM);

    // ---- prep: tf32 (RNA) rounding of GEMM1 operands ----
    {
        int n4;
        n4 = MROWS * DMODEL / 4;
        round_tf32_kernel<<<(n4 + 255) / 256, 256>>>((const float4*)x, (float4*)xr, n4);
        n4 = DMODEL * QKVCOLS / 4;
        round_tf32_kernel<<<(n4 + 255) / 256, 256>>>((const float4*)w_qkv, (float4*)wq, n4);
        n4 = DMODEL * DMODEL / 4;
        round_tf32_kernel<<<(n4 + 255) / 256, 256>>>((const float4*)w_out, (float4*)wo, n4);
    }

    // 1) QKV projection (rounds output to tf32 for raw streaming)
    gemm_tf32_ca<1><<<dim3(QKVCOLS / 256, MROWS / 128), 256, GSMEM>>>(
        xr, wq, qkv_buf, QKVCOLS, DMODEL);

    // 2) causal flash attention (BR=128, cp.async pipelined)
    flash_tf32<<<dim3(SEQ / FBR, BATCH * NHEADS), 256, FSMEM>>>(qkv_buf, attn_buf);

    // 3) output projection (raw fp32 output)
    gemm_tf32_ca<0><<<dim3(DMODEL / 256, MROWS / 128), 256, GSMEM>>>(
        attn_buf, wo, out, DMODEL, DMODEL);
}

// round 15
// speedup vs baseline: 1.9866x; 1.9866x over previous
#include <cuda_runtime.h>
#include <cuda_fp16.h>
#include <math.h>
#include <stdint.h>

// ---------------- problem constants ----------------
#define BATCH   4
#define SEQ     2048
#define DMODEL  1024
#define NHEADS  16
#define DK      64
#define MROWS   (BATCH * SEQ)      // 8192
#define QKVCOLS (3 * DMODEL)       // 3072

// ---------------- scratch ----------------
__device__ __half g_qkvh[(size_t)MROWS * QKVCOLS];   // 48 MB (fp16, from GEMM1)
__device__ __half g_attnh[(size_t)MROWS * DMODEL];   // 16 MB (fp16, from flash)
__device__ __half g_xh[(size_t)MROWS * DMODEL];      // 16 MB
__device__ __half g_wqh[(size_t)DMODEL * QKVCOLS];   //  6 MB
__device__ __half g_woh[(size_t)DMODEL * DMODEL];    //  2 MB

// ---------------- helpers ----------------
__device__ __forceinline__ uint32_t smem_u32(const void* p) {
    uint32_t a;
    asm("{ .reg .u64 t; cvta.to.shared.u64 t, %1; cvt.u32.u64 %0, t; }" : "=r"(a) : "l"(p));
    return a;
}
__device__ __forceinline__ void cp16(uint32_t dst, const void* src) {
    asm volatile("cp.async.cg.shared.global [%0], [%1], 16;" :: "r"(dst), "l"(src));
}
__device__ __forceinline__ void cp_commit() { asm volatile("cp.async.commit_group;"); }
__device__ __forceinline__ void cp_wait0()  { asm volatile("cp.async.wait_group 0;"); }
__device__ __forceinline__ void cp_wait2()  { asm volatile("cp.async.wait_group 2;"); }

__device__ __forceinline__ void ldsm4(uint32_t* r, uint32_t addr) {
    asm volatile("ldmatrix.sync.aligned.m8n8.x4.shared.b16 {%0,%1,%2,%3}, [%4];"
                 : "=r"(r[0]), "=r"(r[1]), "=r"(r[2]), "=r"(r[3]) : "r"(addr));
}
__device__ __forceinline__ void ldsm4t(uint32_t* r, uint32_t addr) {
    asm volatile("ldmatrix.sync.aligned.m8n8.x4.trans.shared.b16 {%0,%1,%2,%3}, [%4];"
                 : "=r"(r[0]), "=r"(r[1]), "=r"(r[2]), "=r"(r[3]) : "r"(addr));
}
// D(16x8) += A(16x16 row) * B(16x8 col), fp16 in, fp32 accum
__device__ __forceinline__ void mma16(float* c, const uint32_t* a, const uint32_t* b) {
    asm volatile(
        "mma.sync.aligned.m16n8k16.row.col.f32.f16.f16.f32 "
        "{%0,%1,%2,%3}, {%4,%5,%6,%7}, {%8,%9}, {%0,%1,%2,%3};"
        : "+f"(c[0]), "+f"(c[1]), "+f"(c[2]), "+f"(c[3])
        : "r"(a[0]), "r"(a[1]), "r"(a[2]), "r"(a[3]), "r"(b[0]), "r"(b[1]));
}
__device__ __forceinline__ uint32_t pack_h2(float x, float y) {
    __half2 h = __floats2half2_rn(x, y);
    return *(uint32_t*)&h;
}

// =================================================================
// FP16 GEMM via mma.m16n8k16 + ldmatrix, cp.async 4-stage pipeline.
// C[M,N] = A[M,K] @ B[K,N], A/B fp16 row-major, accum fp32.
// Block 128x256, 256 thr = 8 warps (2x4), warp tile 64x64, BK=32.
// OUTH=1: store fp16 (half2); OUTH=0: store fp32.
// =================================================================
#define GST 4
#define ASTRH 40                 // A smem row stride in halves (20 words == 20 mod 32)
#define BSTRH 264                // B smem row stride in halves (132 words == 4 mod 32)
#define ASZH (128 * ASTRH)       // halves per A stage
#define BSZH (32 * BSTRH)        // halves per B stage
#define GSMEM ((GST * (ASZH + BSZH)) * 2)   // 108544 B

template <int OUTH>
__global__ __launch_bounds__(256, 1)
void gemm_f16(const __half* __restrict__ A, const __half* __restrict__ B,
              void* __restrict__ Cv, int N, int K)
{
    extern __shared__ __half smh[];
    __half* Asm = smh;                       // [GST][ASZH]
    __half* Bsm = smh + GST * ASZH;          // [GST][BSZH]
    const uint32_t sA = smem_u32(Asm);
    const uint32_t sB = smem_u32(Bsm);

    const int tid  = threadIdx.x, lane = tid & 31, warp = tid >> 5;
    const int g    = lane >> 2, tig = lane & 3;
    const int wr   = warp >> 2, wc  = warp & 3;     // 2 x 4 warp grid
    const int bm   = blockIdx.y * 128, bn = blockIdx.x * 256;
    const int NK   = K / 32;

    auto issue = [&](int s, int kt) {
        const __half* Ag = A + (size_t)bm * K + kt * 32;
        const __half* Bg = B + (size_t)(kt * 32) * N + bn;
        const uint32_t ao = sA + s * ASZH * 2;
        const uint32_t bo = sB + s * BSZH * 2;
        #pragma unroll
        for (int j = 0; j < 2; j++) {        // A: 128 rows x 4 chunks = 512
            int idx = tid + j * 256;
            int row = idx >> 2, cc = (idx & 3) * 8;
            cp16(ao + (row * ASTRH + cc) * 2, Ag + (size_t)row * K + cc);
        }
        #pragma unroll
        for (int j = 0; j < 4; j++) {        // B: 32 rows x 32 chunks = 1024
            int idx = tid + j * 256;
            int row = idx >> 5, cc = (idx & 31) * 8;
            cp16(bo + (row * BSTRH + cc) * 2, Bg + (size_t)row * N + cc);
        }
        cp_commit();
    };

    float acc[4][8][4];
    #pragma unroll
    for (int mt = 0; mt < 4; mt++)
        #pragma unroll
        for (int nt = 0; nt < 8; nt++)
            #pragma unroll
            for (int j = 0; j < 4; j++) acc[mt][nt][j] = 0.0f;

    issue(0, 0);
    issue(1, 1);
    issue(2, 2);

    for (int kt = 0; kt < NK; kt++) {
        cp_wait2();
        __syncthreads();
        if (kt + 3 < NK) issue((kt + 3) & 3, kt + 3);
        else             cp_commit();

        const uint32_t Ab = sA + (kt & 3) * ASZH * 2;
        const uint32_t Bb = sB + (kt & 3) * BSZH * 2;

        #pragma unroll
        for (int kc = 0; kc < 2; kc++) {     // two k16 chunks
            uint32_t a[4][4], b[4][4];       // b[ntp] covers nt=2ntp, 2ntp+1
            #pragma unroll
            for (int mt = 0; mt < 4; mt++) {
                int row = wr * 64 + mt * 16 + (lane & 15);
                int col = kc * 16 + (lane >> 4) * 8;
                ldsm4(a[mt], Ab + (row * ASTRH + col) * 2);
            }
            #pragma unroll
            for (int ntp = 0; ntp < 4; ntp++) {
                int row = kc * 16 + ((lane >> 3) & 1) * 8 + (lane & 7);
                int col = wc * 64 + ntp * 16 + (lane >> 4) * 8;
                ldsm4t(b[ntp], Bb + (row * BSTRH + col) * 2);
            }
            #pragma unroll
            for (int mt = 0; mt < 4; mt++)
                #pragma unroll
                for (int ntp = 0; ntp < 4; ntp++) {
                    mma16(acc[mt][2 * ntp],     a[mt], b[ntp]);
                    mma16(acc[mt][2 * ntp + 1], a[mt], b[ntp] + 2);
                }
        }
    }

    #pragma unroll
    for (int mt = 0; mt < 4; mt++) {
        int row = bm + wr * 64 + mt * 16 + g;
        #pragma unroll
        for (int nt = 0; nt < 8; nt++) {
            int col = bn + wc * 64 + nt * 8 + 2 * tig;
            if (OUTH) {
                __half* C = (__half*)Cv;
                *(uint32_t*)(C + (size_t)row * N + col) =
                    pack_h2(acc[mt][nt][0], acc[mt][nt][1]);
                *(uint32_t*)(C + (size_t)(row + 8) * N + col) =
                    pack_h2(acc[mt][nt][2], acc[mt][nt][3]);
            } else {
                float* C = (float*)Cv;
                *(float2*)(C + (size_t)row * N + col) =
                    make_float2(acc[mt][nt][0], acc[mt][nt][1]);
                *(float2*)(C + (size_t)(row + 8) * N + col) =
                    make_float2(acc[mt][nt][2], acc[mt][nt][3]);
            }
        }
    }
}

// =================================================================
// prep: fp32 -> fp16 (RN) elementwise
// =================================================================
__global__ void f2h_kernel(const float4* __restrict__ in,
                           uint2* __restrict__ out, int n4)
{
    int i = blockIdx.x * blockDim.x + threadIdx.x;
    if (i < n4) {
        float4 v = in[i];
        uint2 r;
        r.x = pack_h2(v.x, v.y);
        r.y = pack_h2(v.z, v.w);
        out[i] = r;
    }
}

// =================================================================
// FP16 flash attention, causal. BR=BC=64, 128 thr (4 warps).
// Warp w owns q rows [16w, 16w+16). Double-buffered cp.async K/V.
// Scale 0.125 applied post-MMA (exact). smem 46080 B -> 3-4 CTAs/SM.
// =================================================================
#define FQST 72                              // halves (36 words == 4 mod 32)
#define FTILE (64 * FQST)                    // halves per 64x64 tile buffer
#define FSMEM (5 * FTILE * 2)                // Q/P + 2K + 2V = 46080 B

__global__ __launch_bounds__(128)
void flash_f16(const __half* __restrict__ qkv, __half* __restrict__ outp)
{
    extern __shared__ __half smh[];
    __half* Qs  = smh;                       // Q staging, then P
    __half* Kst = smh + FTILE;               // [2][FTILE]
    __half* Vst = Kst + 2 * FTILE;
    const uint32_t sQ = smem_u32(Qs);
    const uint32_t sK = smem_u32(Kst);
    const uint32_t sV = smem_u32(Vst);

    const int tid  = threadIdx.x;
    const int lane = tid & 31, warp = tid >> 5;
    const int g    = lane >> 2, tig = lane & 3;
    const int bh   = blockIdx.y, b = bh >> 4, h = bh & 15;
    const int qt   = gridDim.x - 1 - blockIdx.x;   // heavy tiles first
    const int q0   = qt * 64;

    const __half* Qb = qkv + (size_t)b * SEQ * QKVCOLS + h * DK;
    const __half* Kb = Qb + DMODEL;
    const __half* Vb = Qb + 2 * DMODEL;

    auto issue_kv = [&](int s, int kt) {
        const __half* Kg = Kb + (size_t)(kt * 64) * QKVCOLS;
        const __half* Vg = Vb + (size_t)(kt * 64) * QKVCOLS;
        const uint32_t ko = sK + s * FTILE * 2;
        const uint32_t vo = sV + s * FTILE * 2;
        #pragma unroll
        for (int j = 0; j < 4; j++) {        // 64 rows x 8 chunks = 512 each
            int idx = tid + j * 128;
            int row = idx >> 3, cc = (idx & 7) * 8;
            cp16(ko + (row * FQST + cc) * 2, Kg + (size_t)row * QKVCOLS + cc);
            cp16(vo + (row * FQST + cc) * 2, Vg + (size_t)row * QKVCOLS + cc);
        }
        cp_commit();
    };

    issue_kv(0, 0);

    // stage Q (raw fp16 bits; 1/8 scale applied post-MMA)
    for (int i = tid; i < 64 * 8; i += 128) {
        int row = i >> 3, cc = (i & 7) * 8;
        *(uint4*)(Qs + row * FQST + cc) =
            *(const uint4*)(Qb + (size_t)(q0 + row) * QKVCOLS + cc);
    }
    __syncthreads();

    // Q fragments: rows warp*16..+15, 4 k16 chunks over dk=64
    uint32_t aq[4][4];
    #pragma unroll
    for (int kc = 0; kc < 4; kc++) {
        int row = warp * 16 + (lane & 15);
        int col = kc * 16 + (lane >> 4) * 8;
        ldsm4(aq[kc], sQ + (row * FQST + col) * 2);
    }

    float m0 = -INFINITY, m1 = -INFINITY, l0 = 0.0f, l1 = 0.0f;
    float o[8][4];
    #pragma unroll
    for (int nt = 0; nt < 8; nt++)
        #pragma unroll
        for (int j = 0; j < 4; j++) o[nt][j] = 0.0f;

    for (int kt = 0; kt <= qt; kt++) {
        cp_wait0();
        __syncthreads();
        if (kt < qt) issue_kv((kt + 1) & 1, kt + 1);

        const uint32_t Kbb = sK + (kt & 1) * FTILE * 2;
        const uint32_t Vbb = sV + (kt & 1) * FTILE * 2;

        // S = Q K^T  (K frags non-trans: keys are rows)
        float s[8][4];
        #pragma unroll
        for (int nt = 0; nt < 8; nt++)
            s[nt][0] = s[nt][1] = s[nt][2] = s[nt][3] = 0.0f;
        #pragma unroll
        for (int kc = 0; kc < 4; kc++) {
            uint32_t bk[4][4];
            #pragma unroll
            for (int ntp = 0; ntp < 4; ntp++) {
                int row = ntp * 16 + (lane >> 4) * 8 + (lane & 7);
                int col = kc * 16 + ((lane >> 3) & 1) * 8;
                ldsm4(bk[ntp], Kbb + (row * FQST + col) * 2);
            }
            #pragma unroll
            for (int ntp = 0; ntp < 4; ntp++) {
                mma16(s[2 * ntp],     aq[kc], bk[ntp]);
                mma16(s[2 * ntp + 1], aq[kc], bk[ntp] + 2);
            }
        }

        // scale (exact 2^-3); causal mask on the diagonal tile
        #pragma unroll
        for (int nt = 0; nt < 8; nt++) {
            s[nt][0] *= 0.125f; s[nt][1] *= 0.125f;
            s[nt][2] *= 0.125f; s[nt][3] *= 0.125f;
        }
        if (kt == qt) {
            int r0 = warp * 16 + g;
            #pragma unroll
            for (int nt = 0; nt < 8; nt++) {
                int c = nt * 8 + 2 * tig;
                if (c     > r0)     s[nt][0] = -INFINITY;
                if (c + 1 > r0)     s[nt][1] = -INFINITY;
                if (c     > r0 + 8) s[nt][2] = -INFINITY;
                if (c + 1 > r0 + 8) s[nt][3] = -INFINITY;
            }
        }

        // online softmax (rows g, g+8), quad reduction
        float mt0 = -INFINITY, mt1 = -INFINITY;
        #pragma unroll
        for (int nt = 0; nt < 8; nt++) {
            mt0 = fmaxf(mt0, fmaxf(s[nt][0], s[nt][1]));
            mt1 = fmaxf(mt1, fmaxf(s[nt][2], s[nt][3]));
        }
        mt0 = fmaxf(mt0, __shfl_xor_sync(0xffffffffu, mt0, 1));
        mt0 = fmaxf(mt0, __shfl_xor_sync(0xffffffffu, mt0, 2));
        mt1 = fmaxf(mt1, __shfl_xor_sync(0xffffffffu, mt1, 1));
        mt1 = fmaxf(mt1, __shfl_xor_sync(0xffffffffu, mt1, 2));

        float mn0 = fmaxf(m0, mt0), mn1 = fmaxf(m1, mt1);
        float al0 = __expf(m0 - mn0), al1 = __expf(m1 - mn1);

        float rs0 = 0.0f, rs1 = 0.0f;
        #pragma unroll
        for (int nt = 0; nt < 8; nt++) {
            s[nt][0] = __expf(s[nt][0] - mn0);
            s[nt][1] = __expf(s[nt][1] - mn0);
            s[nt][2] = __expf(s[nt][2] - mn1);
            s[nt][3] = __expf(s[nt][3] - mn1);
            rs0 += s[nt][0] + s[nt][1];
            rs1 += s[nt][2] + s[nt][3];
        }
        rs0 += __shfl_xor_sync(0xffffffffu, rs0, 1);
        rs0 += __shfl_xor_sync(0xffffffffu, rs0, 2);
        rs1 += __shfl_xor_sync(0xffffffffu, rs1, 1);
        rs1 += __shfl_xor_sync(0xffffffffu, rs1, 2);

        l0 = l0 * al0 + rs0;
        l1 = l1 * al1 + rs1;
        m0 = mn0;
        m1 = mn1;
        #pragma unroll
        for (int nt = 0; nt < 8; nt++) {
            o[nt][0] *= al0; o[nt][1] *= al0;
            o[nt][2] *= al1; o[nt][3] *= al1;
        }

        // P (fp16) to this warp's private rows of Qs/Ps
        __syncwarp();
        {
            __half* pr0 = Qs + (warp * 16 + g) * FQST;
            __half* pr1 = pr0 + 8 * FQST;
            #pragma unroll
            for (int nt = 0; nt < 8; nt++) {
                int c = nt * 8 + 2 * tig;
                *(uint32_t*)(pr0 + c) = pack_h2(s[nt][0], s[nt][1]);
                *(uint32_t*)(pr1 + c) = pack_h2(s[nt][2], s[nt][3]);
            }
        }
        __syncwarp();

        // O += P @ V  (P frags row-major; V frags trans)
        #pragma unroll
        for (int kc = 0; kc < 4; kc++) {
            uint32_t ap[4];
            {
                int row = warp * 16 + (lane & 15);
                int col = kc * 16 + (lane >> 4) * 8;
                ldsm4(ap, sQ + (row * FQST + col) * 2);
            }
            uint32_t bv[4][4];
            #pragma unroll
            for (int ntp = 0; ntp < 4; ntp++) {
                int row = kc * 16 + ((lane >> 3) & 1) * 8 + (lane & 7);
                int col = ntp * 16 + (lane >> 4) * 8;
                ldsm4t(bv[ntp], Vbb + (row * FQST + col) * 2);
            }
            #pragma unroll
            for (int ntp = 0; ntp < 4; ntp++) {
                mma16(o[2 * ntp],     ap, bv[ntp]);
                mma16(o[2 * ntp + 1], ap, bv[ntp] + 2);
            }
        }
    }

    // normalize + fp16 store (GEMM2 streams these bits raw)
    float i0 = 1.0f / l0, i1 = 1.0f / l1;
    int r0 = q0 + warp * 16 + g;
    __half* dst0 = outp + (size_t)(b * SEQ + r0) * DMODEL + h * DK;
    __half* dst1 = dst0 + (size_t)8 * DMODEL;
    #pragma unroll
    for (int nt = 0; nt < 8; nt++) {
        int c = nt * 8 + 2 * tig;
        *(uint32_t*)(dst0 + c) = pack_h2(o[nt][0] * i0, o[nt][1] * i0);
        *(uint32_t*)(dst1 + c) = pack_h2(o[nt][2] * i1, o[nt][3] * i1);
    }
}

// =================================================================
// kernel_launch
// =================================================================
extern "C" void kernel_launch(void* const* d_in, const int* in_sizes, int n_in,
                              void* d_out, int out_size)
{
    const float* x     = (const float*)d_in[0];
    const float* w_qkv = (const float*)d_in[1];
    const float* w_out = (const float*)d_in[2];
    float*       out   = (float*)d_out;

    __half *qkvh, *attnh, *xh, *wqh, *woh;
    cudaGetSymbolAddress((void**)&qkvh,  g_qkvh);
    cudaGetSymbolAddress((void**)&attnh, g_attnh);
    cudaGetSymbolAddress((void**)&xh,    g_xh);
    cudaGetSymbolAddress((void**)&wqh,   g_wqh);
    cudaGetSymbolAddress((void**)&woh,   g_woh);

    cudaFuncSetAttribute(gemm_f16<1>, cudaFuncAttributeMaxDynamicSharedMemorySize, GSMEM);
    cudaFuncSetAttribute(gemm_f16<0>, cudaFuncAttributeMaxDynamicSharedMemorySize, GSMEM);
    cudaFuncSetAttribute(flash_f16, cudaFuncAttributeMaxDynamicSharedMemorySize, FSMEM);

    // ---- prep: fp16 (RN) rounding of GEMM1 operands ----
    {
        int n4;
        n4 = MROWS * DMODEL / 4;
        f2h_kernel<<<(n4 + 255) / 256, 256>>>((const float4*)x, (uint2*)xh, n4);
        n4 = DMODEL * QKVCOLS / 4;
        f2h_kernel<<<(n4 + 255) / 256, 256>>>((const float4*)w_qkv, (uint2*)wqh, n4);
        n4 = DMODEL * DMODEL / 4;
        f2h_kernel<<<(n4 + 255) / 256, 256>>>((const float4*)w_out, (uint2*)woh, n4);
    }

    // 1) QKV projection: fp16 in, fp16 out
    gemm_f16<1><<<dim3(QKVCOLS / 256, MROWS / 128), 256, GSMEM>>>(
        xh, wqh, qkvh, QKVCOLS, DMODEL);

    // 2) causal flash attention: fp16 in/out, fp32 softmax/accum
    flash_f16<<<dim3(SEQ / 64, BATCH * NHEADS), 128, FSMEM>>>(qkvh, attnh);

    // 3) output projection: fp16 in, fp32 out
    gemm_f16<0><<<dim3(DMODEL / 256, MROWS / 128), 256, GSMEM>>>(
        attnh, woh, out, DMODEL, DMODEL);
}

// round 17
// speedup vs baseline: 1.9919x; 1.0026x over previous
#include <cuda_runtime.h>
#include <cuda_fp16.h>
#include <math.h>
#include <stdint.h>

// ---------------- problem constants ----------------
#define BATCH   4
#define SEQ     2048
#define DMODEL  1024
#define NHEADS  16
#define DK      64
#define MROWS   (BATCH * SEQ)      // 8192
#define QKVCOLS (3 * DMODEL)       // 3072

// ---------------- scratch ----------------
__device__ __half g_qkvh[(size_t)MROWS * QKVCOLS];   // 48 MB (fp16, from GEMM1)
__device__ __half g_attnh[(size_t)MROWS * DMODEL];   // 16 MB (fp16, from flash)
__device__ __half g_xh[(size_t)MROWS * DMODEL];      // 16 MB
__device__ __half g_wqh[(size_t)DMODEL * QKVCOLS];   //  6 MB
__device__ __half g_woh[(size_t)DMODEL * DMODEL];    //  2 MB

// ---------------- helpers ----------------
__device__ __forceinline__ uint32_t smem_u32(const void* p) {
    uint32_t a;
    asm("{ .reg .u64 t; cvta.to.shared.u64 t, %1; cvt.u32.u64 %0, t; }" : "=r"(a) : "l"(p));
    return a;
}
__device__ __forceinline__ void cp16(uint32_t dst, const void* src) {
    asm volatile("cp.async.cg.shared.global [%0], [%1], 16;" :: "r"(dst), "l"(src));
}
__device__ __forceinline__ void cp_commit() { asm volatile("cp.async.commit_group;"); }
__device__ __forceinline__ void cp_wait0()  { asm volatile("cp.async.wait_group 0;"); }
__device__ __forceinline__ void cp_wait2()  { asm volatile("cp.async.wait_group 2;"); }

__device__ __forceinline__ void ldsm4(uint32_t* r, uint32_t addr) {
    asm volatile("ldmatrix.sync.aligned.m8n8.x4.shared.b16 {%0,%1,%2,%3}, [%4];"
                 : "=r"(r[0]), "=r"(r[1]), "=r"(r[2]), "=r"(r[3]) : "r"(addr));
}
__device__ __forceinline__ void ldsm4t(uint32_t* r, uint32_t addr) {
    asm volatile("ldmatrix.sync.aligned.m8n8.x4.trans.shared.b16 {%0,%1,%2,%3}, [%4];"
                 : "=r"(r[0]), "=r"(r[1]), "=r"(r[2]), "=r"(r[3]) : "r"(addr));
}
// D(16x8) += A(16x16 row) * B(16x8 col), fp16 in, fp32 accum
__device__ __forceinline__ void mma16(float* c, const uint32_t* a, const uint32_t* b) {
    asm volatile(
        "mma.sync.aligned.m16n8k16.row.col.f32.f16.f16.f32 "
        "{%0,%1,%2,%3}, {%4,%5,%6,%7}, {%8,%9}, {%0,%1,%2,%3};"
        : "+f"(c[0]), "+f"(c[1]), "+f"(c[2]), "+f"(c[3])
        : "r"(a[0]), "r"(a[1]), "r"(a[2]), "r"(a[3]), "r"(b[0]), "r"(b[1]));
}
__device__ __forceinline__ uint32_t pack_h2(float x, float y) {
    __half2 h = __floats2half2_rn(x, y);
    return *(uint32_t*)&h;
}

// =================================================================
// FP16 GEMM via mma.m16n8k16 + ldmatrix, cp.async 4-stage pipeline.
// C[M,N] = A[M,K] @ B[K,N], A/B fp16 row-major, accum fp32.
// Block 128x256, 256 thr = 8 warps (2x4), warp tile 64x64, BK=32.
// OUTH=1: store fp16 (half2); OUTH=0: store fp32.
// =================================================================
#define GST 4
#define ASTRH 40                 // A smem row stride in halves (20 words == 20 mod 32)
#define BSTRH 264                // B smem row stride in halves (132 words == 4 mod 32)
#define ASZH (128 * ASTRH)       // halves per A stage
#define BSZH (32 * BSTRH)        // halves per B stage
#define GSMEM ((GST * (ASZH + BSZH)) * 2)   // 108544 B

template <int OUTH>
__global__ __launch_bounds__(256, 1)
void gemm_f16(const __half* __restrict__ A, const __half* __restrict__ B,
              void* __restrict__ Cv, int N, int K)
{
    extern __shared__ __half smh[];
    __half* Asm = smh;                       // [GST][ASZH]
    __half* Bsm = smh + GST * ASZH;          // [GST][BSZH]
    const uint32_t sA = smem_u32(Asm);
    const uint32_t sB = smem_u32(Bsm);

    const int tid  = threadIdx.x, lane = tid & 31, warp = tid >> 5;
    const int g    = lane >> 2, tig = lane & 3;
    const int wr   = warp >> 2, wc  = warp & 3;     // 2 x 4 warp grid
    const int bm   = blockIdx.y * 128, bn = blockIdx.x * 256;
    const int NK   = K / 32;

    auto issue = [&](int s, int kt) {
        const __half* Ag = A + (size_t)bm * K + kt * 32;
        const __half* Bg = B + (size_t)(kt * 32) * N + bn;
        const uint32_t ao = sA + s * ASZH * 2;
        const uint32_t bo = sB + s * BSZH * 2;
        #pragma unroll
        for (int j = 0; j < 2; j++) {        // A: 128 rows x 4 chunks = 512
            int idx = tid + j * 256;
            int row = idx >> 2, cc = (idx & 3) * 8;
            cp16(ao + (row * ASTRH + cc) * 2, Ag + (size_t)row * K + cc);
        }
        #pragma unroll
        for (int j = 0; j < 4; j++) {        // B: 32 rows x 32 chunks = 1024
            int idx = tid + j * 256;
            int row = idx >> 5, cc = (idx & 31) * 8;
            cp16(bo + (row * BSTRH + cc) * 2, Bg + (size_t)row * N + cc);
        }
        cp_commit();
    };

    float acc[4][8][4];
    #pragma unroll
    for (int mt = 0; mt < 4; mt++)
        #pragma unroll
        for (int nt = 0; nt < 8; nt++)
            #pragma unroll
            for (int j = 0; j < 4; j++) acc[mt][nt][j] = 0.0f;

    issue(0, 0);
    issue(1, 1);
    issue(2, 2);

    for (int kt = 0; kt < NK; kt++) {
        cp_wait2();
        __syncthreads();
        if (kt + 3 < NK) issue((kt + 3) & 3, kt + 3);
        else             cp_commit();

        const uint32_t Ab = sA + (kt & 3) * ASZH * 2;
        const uint32_t Bb = sB + (kt & 3) * BSZH * 2;

        #pragma unroll
        for (int kc = 0; kc < 2; kc++) {     // two k16 chunks
            uint32_t a[4][4], b[4][4];       // b[ntp] covers nt=2ntp, 2ntp+1
            #pragma unroll
            for (int mt = 0; mt < 4; mt++) {
                int row = wr * 64 + mt * 16 + (lane & 15);
                int col = kc * 16 + (lane >> 4) * 8;
                ldsm4(a[mt], Ab + (row * ASTRH + col) * 2);
            }
            #pragma unroll
            for (int ntp = 0; ntp < 4; ntp++) {
                int row = kc * 16 + ((lane >> 3) & 1) * 8 + (lane & 7);
                int col = wc * 64 + ntp * 16 + (lane >> 4) * 8;
                ldsm4t(b[ntp], Bb + (row * BSTRH + col) * 2);
            }
            #pragma unroll
            for (int mt = 0; mt < 4; mt++)
                #pragma unroll
                for (int ntp = 0; ntp < 4; ntp++) {
                    mma16(acc[mt][2 * ntp],     a[mt], b[ntp]);
                    mma16(acc[mt][2 * ntp + 1], a[mt], b[ntp] + 2);
                }
        }
    }

    #pragma unroll
    for (int mt = 0; mt < 4; mt++) {
        int row = bm + wr * 64 + mt * 16 + g;
        #pragma unroll
        for (int nt = 0; nt < 8; nt++) {
            int col = bn + wc * 64 + nt * 8 + 2 * tig;
            if (OUTH) {
                __half* C = (__half*)Cv;
                *(uint32_t*)(C + (size_t)row * N + col) =
                    pack_h2(acc[mt][nt][0], acc[mt][nt][1]);
                *(uint32_t*)(C + (size_t)(row + 8) * N + col) =
                    pack_h2(acc[mt][nt][2], acc[mt][nt][3]);
            } else {
                float* C = (float*)Cv;
                *(float2*)(C + (size_t)row * N + col) =
                    make_float2(acc[mt][nt][0], acc[mt][nt][1]);
                *(float2*)(C + (size_t)(row + 8) * N + col) =
                    make_float2(acc[mt][nt][2], acc[mt][nt][3]);
            }
        }
    }
}

// =================================================================
// prep: fp32 -> fp16 (RN) elementwise
// =================================================================
__global__ void f2h_kernel(const float4* __restrict__ in,
                           uint2* __restrict__ out, int n4)
{
    int i = blockIdx.x * blockDim.x + threadIdx.x;
    if (i < n4) {
        float4 v = in[i];
        uint2 r;
        r.x = pack_h2(v.x, v.y);
        r.y = pack_h2(v.z, v.w);
        out[i] = r;
    }
}

// =================================================================
// FP16 flash attention, causal. BR=BC=64, 128 thr (4 warps).
// Warp w owns q rows [16w, 16w+16). Double-buffered cp.async K/V.
// Scale 0.125 applied post-MMA (exact). smem 46080 B -> 3-4 CTAs/SM.
// =================================================================
#define FQST 72                              // halves (36 words == 4 mod 32)
#define FTILE (64 * FQST)                    // halves per 64x64 tile buffer
#define FSMEM (5 * FTILE * 2)                // Q/P + 2K + 2V = 46080 B

__global__ __launch_bounds__(128)
void flash_f16(const __half* __restrict__ qkv, __half* __restrict__ outp)
{
    extern __shared__ __half smh[];
    __half* Qs  = smh;                       // Q staging, then P
    __half* Kst = smh + FTILE;               // [2][FTILE]
    __half* Vst = Kst + 2 * FTILE;
    const uint32_t sQ = smem_u32(Qs);
    const uint32_t sK = smem_u32(Kst);
    const uint32_t sV = smem_u32(Vst);

    const int tid  = threadIdx.x;
    const int lane = tid & 31, warp = tid >> 5;
    const int g    = lane >> 2, tig = lane & 3;
    const int bh   = blockIdx.y, b = bh >> 4, h = bh & 15;
    const int qt   = gridDim.x - 1 - blockIdx.x;   // heavy tiles first
    const int q0   = qt * 64;

    const __half* Qb = qkv + (size_t)b * SEQ * QKVCOLS + h * DK;
    const __half* Kb = Qb + DMODEL;
    const __half* Vb = Qb + 2 * DMODEL;

    auto issue_kv = [&](int s, int kt) {
        const __half* Kg = Kb + (size_t)(kt * 64) * QKVCOLS;
        const __half* Vg = Vb + (size_t)(kt * 64) * QKVCOLS;
        const uint32_t ko = sK + s * FTILE * 2;
        const uint32_t vo = sV + s * FTILE * 2;
        #pragma unroll
        for (int j = 0; j < 4; j++) {        // 64 rows x 8 chunks = 512 each
            int idx = tid + j * 128;
            int row = idx >> 3, cc = (idx & 7) * 8;
            cp16(ko + (row * FQST + cc) * 2, Kg + (size_t)row * QKVCOLS + cc);
            cp16(vo + (row * FQST + cc) * 2, Vg + (size_t)row * QKVCOLS + cc);
        }
        cp_commit();
    };

    issue_kv(0, 0);

    // stage Q (raw fp16 bits; 1/8 scale applied post-MMA)
    for (int i = tid; i < 64 * 8; i += 128) {
        int row = i >> 3, cc = (i & 7) * 8;
        *(uint4*)(Qs + row * FQST + cc) =
            *(const uint4*)(Qb + (size_t)(q0 + row) * QKVCOLS + cc);
    }
    __syncthreads();

    // Q fragments: rows warp*16..+15, 4 k16 chunks over dk=64
    uint32_t aq[4][4];
    #pragma unroll
    for (int kc = 0; kc < 4; kc++) {
        int row = warp * 16 + (lane & 15);
        int col = kc * 16 + (lane >> 4) * 8;
        ldsm4(aq[kc], sQ + (row * FQST + col) * 2);
    }

    float m0 = -INFINITY, m1 = -INFINITY, l0 = 0.0f, l1 = 0.0f;
    float o[8][4];
    #pragma unroll
    for (int nt = 0; nt < 8; nt++)
        #pragma unroll
        for (int j = 0; j < 4; j++) o[nt][j] = 0.0f;

    for (int kt = 0; kt <= qt; kt++) {
        cp_wait0();
        __syncthreads();
        if (kt < qt) issue_kv((kt + 1) & 1, kt + 1);

        const uint32_t Kbb = sK + (kt & 1) * FTILE * 2;
        const uint32_t Vbb = sV + (kt & 1) * FTILE * 2;

        // S = Q K^T  (K frags non-trans: keys are rows)
        float s[8][4];
        #pragma unroll
        for (int nt = 0; nt < 8; nt++)
            s[nt][0] = s[nt][1] = s[nt][2] = s[nt][3] = 0.0f;
        #pragma unroll
        for (int kc = 0; kc < 4; kc++) {
            uint32_t bk[4][4];
            #pragma unroll
            for (int ntp = 0; ntp < 4; ntp++) {
                int row = ntp * 16 + (lane >> 4) * 8 + (lane & 7);
                int col = kc * 16 + ((lane >> 3) & 1) * 8;
                ldsm4(bk[ntp], Kbb + (row * FQST + col) * 2);
            }
            #pragma unroll
            for (int ntp = 0; ntp < 4; ntp++) {
                mma16(s[2 * ntp],     aq[kc], bk[ntp]);
                mma16(s[2 * ntp + 1], aq[kc], bk[ntp] + 2);
            }
        }

        // scale (exact 2^-3); causal mask on the diagonal tile
        #pragma unroll
        for (int nt = 0; nt < 8; nt++) {
            s[nt][0] *= 0.125f; s[nt][1] *= 0.125f;
            s[nt][2] *= 0.125f; s[nt][3] *= 0.125f;
        }
        if (kt == qt) {
            int r0 = warp * 16 + g;
            #pragma unroll
            for (int nt = 0; nt < 8; nt++) {
                int c = nt * 8 + 2 * tig;
                if (c     > r0)     s[nt][0] = -INFINITY;
                if (c + 1 > r0)     s[nt][1] = -INFINITY;
                if (c     > r0 + 8) s[nt][2] = -INFINITY;
                if (c + 1 > r0 + 8) s[nt][3] = -INFINITY;
            }
        }

        // online softmax (rows g, g+8), quad reduction
        float mt0 = -INFINITY, mt1 = -INFINITY;
        #pragma unroll
        for (int nt = 0; nt < 8; nt++) {
            mt0 = fmaxf(mt0, fmaxf(s[nt][0], s[nt][1]));
            mt1 = fmaxf(mt1, fmaxf(s[nt][2], s[nt][3]));
        }
        mt0 = fmaxf(mt0, __shfl_xor_sync(0xffffffffu, mt0, 1));
        mt0 = fmaxf(mt0, __shfl_xor_sync(0xffffffffu, mt0, 2));
        mt1 = fmaxf(mt1, __shfl_xor_sync(0xffffffffu, mt1, 1));
        mt1 = fmaxf(mt1, __shfl_xor_sync(0xffffffffu, mt1, 2));

        float mn0 = fmaxf(m0, mt0), mn1 = fmaxf(m1, mt1);
        float al0 = __expf(m0 - mn0), al1 = __expf(m1 - mn1);

        float rs0 = 0.0f, rs1 = 0.0f;
        #pragma unroll
        for (int nt = 0; nt < 8; nt++) {
            s[nt][0] = __expf(s[nt][0] - mn0);
            s[nt][1] = __expf(s[nt][1] - mn0);
            s[nt][2] = __expf(s[nt][2] - mn1);
            s[nt][3] = __expf(s[nt][3] - mn1);
            rs0 += s[nt][0] + s[nt][1];
            rs1 += s[nt][2] + s[nt][3];
        }
        rs0 += __shfl_xor_sync(0xffffffffu, rs0, 1);
        rs0 += __shfl_xor_sync(0xffffffffu, rs0, 2);
        rs1 += __shfl_xor_sync(0xffffffffu, rs1, 1);
        rs1 += __shfl_xor_sync(0xffffffffu, rs1, 2);

        l0 = l0 * al0 + rs0;
        l1 = l1 * al1 + rs1;
        m0 = mn0;
        m1 = mn1;
        #pragma unroll
        for (int nt = 0; nt < 8; nt++) {
            o[nt][0] *= al0; o[nt][1] *= al0;
            o[nt][2] *= al1; o[nt][3] *= al1;
        }

        // P (fp16) to this warp's private rows of Qs/Ps
        __syncwarp();
        {
            __half* pr0 = Qs + (warp * 16 + g) * FQST;
            __half* pr1 = pr0 + 8 * FQST;
            #pragma unroll
            for (int nt = 0; nt < 8; nt++) {
                int c = nt * 8 + 2 * tig;
                *(uint32_t*)(pr0 + c) = pack_h2(s[nt][0], s[nt][1]);
                *(uint32_t*)(pr1 + c) = pack_h2(s[nt][2], s[nt][3]);
            }
        }
        __syncwarp();

        // O += P @ V  (P frags row-major; V frags trans)
        #pragma unroll
        for (int kc = 0; kc < 4; kc++) {
            uint32_t ap[4];
            {
                int row = warp * 16 + (lane & 15);
                int col = kc * 16 + (lane >> 4) * 8;
                ldsm4(ap, sQ + (row * FQST + col) * 2);
            }
            uint32_t bv[4][4];
            #pragma unroll
            for (int ntp = 0; ntp < 4; ntp++) {
                int row = kc * 16 + ((lane >> 3) & 1) * 8 + (lane & 7);
                int col = ntp * 16 + (lane >> 4) * 8;
                ldsm4t(bv[ntp], Vbb + (row * FQST + col) * 2);
            }
            #pragma unroll
            for (int ntp = 0; ntp < 4; ntp++) {
                mma16(o[2 * ntp],     ap, bv[ntp]);
                mma16(o[2 * ntp + 1], ap, bv[ntp] + 2);
            }
        }
    }

    // normalize + fp16 store (GEMM2 streams these bits raw)
    float i0 = 1.0f / l0, i1 = 1.0f / l1;
    int r0 = q0 + warp * 16 + g;
    __half* dst0 = outp + (size_t)(b * SEQ + r0) * DMODEL + h * DK;
    __half* dst1 = dst0 + (size_t)8 * DMODEL;
    #pragma unroll
    for (int nt = 0; nt < 8; nt++) {
        int c = nt * 8 + 2 * tig;
        *(uint32_t*)(dst0 + c) = pack_h2(o[nt][0] * i0, o[nt][1] * i0);
        *(uint32_t*)(dst1 + c) = pack_h2(o[nt][2] * i1, o[nt][3] * i1);
    }
}

// =================================================================
// kernel_launch
// =================================================================
extern "C" void kernel_launch(void* const* d_in, const int* in_sizes, int n_in,
                              void* d_out, int out_size)
{
    const float* x     = (const float*)d_in[0];
    const float* w_qkv = (const float*)d_in[1];
    const float* w_out = (const float*)d_in[2];
    float*       out   = (float*)d_out;

    __half *qkvh, *attnh, *xh, *wqh, *woh;
    cudaGetSymbolAddress((void**)&qkvh,  g_qkvh);
    cudaGetSymbolAddress((void**)&attnh, g_attnh);
    cudaGetSymbolAddress((void**)&xh,    g_xh);
    cudaGetSymbolAddress((void**)&wqh,   g_wqh);
    cudaGetSymbolAddress((void**)&woh,   g_woh);

    cudaFuncSetAttribute(gemm_f16<1>, cudaFuncAttributeMaxDynamicSharedMemorySize, GSMEM);
    cudaFuncSetAttribute(gemm_f16<0>, cudaFuncAttributeMaxDynamicSharedMemorySize, GSMEM);
    cudaFuncSetAttribute(flash_f16, cudaFuncAttributeMaxDynamicSharedMemorySize, FSMEM);

    // ---- prep: fp16 (RN) rounding of GEMM1 operands ----
    {
        int n4;
        n4 = MROWS * DMODEL / 4;
        f2h_kernel<<<(n4 + 255) / 256, 256>>>((const float4*)x, (uint2*)xh, n4);
        n4 = DMODEL * QKVCOLS / 4;
        f2h_kernel<<<(n4 + 255) / 256, 256>>>((const float4*)w_qkv, (uint2*)wqh, n4);
        n4 = DMODEL * DMODEL / 4;
        f2h_kernel<<<(n4 + 255) / 256, 256>>>((const float4*)w_out, (uint2*)woh, n4);
    }

    // 1) QKV projection: fp16 in, fp16 out
    gemm_f16<1><<<dim3(QKVCOLS / 256, MROWS / 128), 256, GSMEM>>>(
        xh, wqh, qkvh, QKVCOLS, DMODEL);

    // 2) causal flash attention: fp16 in/out, fp32 softmax/accum
    flash_f16<<<dim3(SEQ / 64, BATCH * NHEADS), 128, FSMEM>>>(qkvh, attnh);

    // 3) output projection: fp16 in, fp32 out
    gemm_f16<0><<<dim3(DMODEL / 256, MROWS / 128), 256, GSMEM>>>(
        attnh, woh, out, DMODEL, DMODEL);
}